// round 8
// baseline (speedup 1.0000x reference)
#include <cuda_runtime.h>
#include <mma.h>
#include <math.h>
#include <stdint.h>

using namespace nvcuda;

#define SEQ 1024
#define CS  1024
#define NH  16
#define HD  64
#define CZ  128

// ---------------- scratch (device globals; no allocation allowed) -------------
__device__ float g_q[SEQ * CS];
__device__ float g_k[SEQ * CS];
__device__ float g_v[SEQ * CS];
__device__ float g_g[SEQ * CS];
__device__ float g_o[SEQ * CS];   // gated o (input to Wo gemm)
__device__ float g_att[(size_t)NH * SEQ * SEQ];   // z (pair bias + mask), 64 MB

// ---------------- cp.async helpers -------------------------------------------
__device__ __forceinline__ uint32_t sptr(const void* p) {
    return (uint32_t)__cvta_generic_to_shared(p);
}
#define CP_ASYNC16(dst, src) \
    asm volatile("cp.async.cg.shared.global [%0], [%1], 16;\n" :: "r"(dst), "l"(src))
#define CP_COMMIT() asm volatile("cp.async.commit_group;\n" ::)
#define CP_WAIT(N)  asm volatile("cp.async.wait_group %0;\n" :: "n"(N))

// =============================================================================
// NT TF32 GEMM body: C[m,n] = sum_k A[m,k]*B[n,k], M=N=K=1024 fixed.
// 128x128 block tile, BK=32, 256 threads, warp tile 32x64, double-buffered
// cp.async. mode 0: plain  1: +bias[n]  2: sigmoid
// Dynamic smem: 2*(128*36)*2 floats = 73728 B  (epilogue reuses as Cs 128x132)
// =============================================================================
#define GEMM_SMEM_BYTES 73728

__device__ __forceinline__ void gemm128_body(
    const float* __restrict__ A, const float* __restrict__ B,
    float* __restrict__ C, const float* __restrict__ bias, int mode,
    int m0, int n0, float* sm)
{
    const int t = threadIdx.x;
    const int w = t >> 5;
    const int m_base = (w >> 1) * 32;   // warp_m 0..3
    const int n_base = (w & 1) * 64;    // warp_n 0..1

    float* As = sm;                 // [2][128][36]
    float* Bs = sm + 2 * 128 * 36;  // [2][128][36]

    const int lrow = t >> 1;               // 0..127
    const int lcol = (t & 1) * 16;         // 0 or 16

    wmma::fragment<wmma::accumulator, 16, 16, 8, float> acc[2][4];
#pragma unroll
    for (int i = 0; i < 2; i++)
#pragma unroll
        for (int j = 0; j < 4; j++) wmma::fill_fragment(acc[i][j], 0.f);

    // prologue: load k-tile 0 into buf 0
    {
        const float* arow = A + (long)(m0 + lrow) * CS + lcol;
        const float* brow = B + (long)(n0 + lrow) * CS + lcol;
        uint32_t da = sptr(&As[lrow * 36 + lcol]);
        uint32_t db = sptr(&Bs[lrow * 36 + lcol]);
#pragma unroll
        for (int i = 0; i < 4; i++) {
            CP_ASYNC16(da + i * 16, arow + i * 4);
            CP_ASYNC16(db + i * 16, brow + i * 4);
        }
        CP_COMMIT();
    }

    const int KT = CS / 32;
    int buf = 0;
    for (int kt = 0; kt < KT; kt++) {
        if (kt + 1 < KT) {
            int nb = buf ^ 1;
            int k0 = (kt + 1) * 32;
            const float* arow = A + (long)(m0 + lrow) * CS + k0 + lcol;
            const float* brow = B + (long)(n0 + lrow) * CS + k0 + lcol;
            uint32_t da = sptr(&As[nb * 4608 + lrow * 36 + lcol]);
            uint32_t db = sptr(&Bs[nb * 4608 + lrow * 36 + lcol]);
#pragma unroll
            for (int i = 0; i < 4; i++) {
                CP_ASYNC16(da + i * 16, arow + i * 4);
                CP_ASYNC16(db + i * 16, brow + i * 4);
            }
            CP_COMMIT();
            CP_WAIT(1);
        } else {
            CP_WAIT(0);
        }
        __syncthreads();

        const float* Ab = As + buf * 4608;
        const float* Bb = Bs + buf * 4608;
#pragma unroll
        for (int kk = 0; kk < 32; kk += 8) {
            wmma::fragment<wmma::matrix_a, 16, 16, 8, wmma::precision::tf32, wmma::row_major> af[2];
            wmma::fragment<wmma::matrix_b, 16, 16, 8, wmma::precision::tf32, wmma::col_major> bf[4];
#pragma unroll
            for (int i = 0; i < 2; i++) {
                wmma::load_matrix_sync(af[i], &Ab[(m_base + 16 * i) * 36 + kk], 36);
#pragma unroll
                for (int e = 0; e < af[i].num_elements; e++)
                    af[i].x[e] = wmma::__float_to_tf32(af[i].x[e]);
            }
#pragma unroll
            for (int j = 0; j < 4; j++) {
                wmma::load_matrix_sync(bf[j], &Bb[(n_base + 16 * j) * 36 + kk], 36);
#pragma unroll
                for (int e = 0; e < bf[j].num_elements; e++)
                    bf[j].x[e] = wmma::__float_to_tf32(bf[j].x[e]);
            }
#pragma unroll
            for (int i = 0; i < 2; i++)
#pragma unroll
                for (int j = 0; j < 4; j++)
                    wmma::mma_sync(acc[i][j], af[i], bf[j], acc[i][j]);
        }
        __syncthreads();
        buf ^= 1;
    }

    // epilogue: stage through smem (reuse as Cs[128][132])
#pragma unroll
    for (int i = 0; i < 2; i++)
#pragma unroll
        for (int j = 0; j < 4; j++)
            wmma::store_matrix_sync(&sm[(m_base + 16 * i) * 132 + n_base + 16 * j],
                                    acc[i][j], 132, wmma::mem_row_major);
    __syncthreads();

    {
        int r = t >> 1;                    // 0..127
        int cbase = (t & 1) * 64;
        long crow = (long)(m0 + r) * CS + n0;
#pragma unroll
        for (int i = 0; i < 16; i++) {
            int c = cbase + i * 4;
            float4 v = *(float4*)&sm[r * 132 + c];
            if (mode == 1) {
                float4 b4 = *(const float4*)&bias[n0 + c];
                v.x += b4.x; v.y += b4.y; v.z += b4.z; v.w += b4.w;
            } else if (mode == 2) {
                v.x = 1.f / (1.f + __expf(-v.x));
                v.y = 1.f / (1.f + __expf(-v.y));
                v.z = 1.f / (1.f + __expf(-v.z));
                v.w = 1.f / (1.f + __expf(-v.w));
            }
            *(float4*)&C[crow + c] = v;
        }
    }
}

// ---------------- zbias body: z[h,i,:] = bias[i,:,:]@Wz + mask term -----------
__device__ void zbias_body(
    int i, const float* __restrict__ bias, const float* __restrict__ Wz,
    const float* __restrict__ mask, float* __restrict__ zout)
{
    __shared__ float wz[CZ * NH];
    int t = threadIdx.x;
    for (int idx = t; idx < CZ * NH; idx += 256) wz[idx] = Wz[idx];
    __syncthreads();

    const float* bp = bias + (size_t)i * SEQ * CZ;

    float acc[4][NH];
#pragma unroll
    for (int p = 0; p < 4; p++)
#pragma unroll
        for (int h = 0; h < NH; h++) acc[p][h] = 0.f;

#pragma unroll 1
    for (int c4 = 0; c4 < CZ / 4; c4++) {
        float bvf[4][4];
#pragma unroll
        for (int p = 0; p < 4; p++) {
            float4 bv = *(const float4*)(bp + (size_t)(t + p * 256) * CZ + c4 * 4);
            bvf[p][0] = bv.x; bvf[p][1] = bv.y; bvf[p][2] = bv.z; bvf[p][3] = bv.w;
        }
#pragma unroll
        for (int cc = 0; cc < 4; cc++) {
            int c = c4 * 4 + cc;
            float4 w0 = *(const float4*)&wz[c * NH + 0];
            float4 w1 = *(const float4*)&wz[c * NH + 4];
            float4 w2 = *(const float4*)&wz[c * NH + 8];
            float4 w3 = *(const float4*)&wz[c * NH + 12];
#pragma unroll
            for (int p = 0; p < 4; p++) {
                float b = bvf[p][cc];
                acc[p][0]  += b * w0.x; acc[p][1]  += b * w0.y; acc[p][2]  += b * w0.z; acc[p][3]  += b * w0.w;
                acc[p][4]  += b * w1.x; acc[p][5]  += b * w1.y; acc[p][6]  += b * w1.z; acc[p][7]  += b * w1.w;
                acc[p][8]  += b * w2.x; acc[p][9]  += b * w2.y; acc[p][10] += b * w2.z; acc[p][11] += b * w2.w;
                acc[p][12] += b * w3.x; acc[p][13] += b * w3.y; acc[p][14] += b * w3.z; acc[p][15] += b * w3.w;
            }
        }
    }

    float mk[4];
#pragma unroll
    for (int p = 0; p < 4; p++)
        mk[p] = (1.0f - mask[t + p * 256]) * (-1000000.0f);

#pragma unroll
    for (int h = 0; h < NH; h++) {
        float* row = zout + ((size_t)h * SEQ + i) * SEQ;
#pragma unroll
        for (int p = 0; p < 4; p++)
            row[t + p * 256] = acc[p][h] + mk[p];
    }
}

// ---------------- stage1: proj GEMM blocks (0..255) + zbias blocks (256..1279)
__global__ __launch_bounds__(256) void stage1_kernel(
    const float* __restrict__ s, const float* __restrict__ k_in,
    const float* __restrict__ Wq, const float* __restrict__ bq,
    const float* __restrict__ Wk, const float* __restrict__ Wv,
    const float* __restrict__ Wg,
    float* __restrict__ q, float* __restrict__ k,
    float* __restrict__ v, float* __restrict__ g,
    const float* __restrict__ bias, const float* __restrict__ Wz,
    const float* __restrict__ mask, float* __restrict__ zout)
{
    extern __shared__ float sm[];
    int bid = blockIdx.x;
    if (bid < 256) {
        int z   = bid >> 6;         // 0..3: q,k,v,g
        int rem = bid & 63;
        int m0  = (rem >> 3) * 128;
        int n0  = (rem & 7) * 128;
        const float* A = (z == 0 || z == 3) ? s : k_in;
        const float* W = (z == 0) ? Wq : (z == 1) ? Wk : (z == 2) ? Wv : Wg;
        float*       C = (z == 0) ? q  : (z == 1) ? k  : (z == 2) ? v  : g;
        int mode       = (z == 0) ? 1  : (z == 3) ? 2  : 0;
        gemm128_body(A, W, C, bq, mode, m0, n0, sm);
    } else {
        zbias_body(bid - 256, bias, Wz, mask, zout);
    }
}

// ---------------- Wo GEMM: out = (gated o) @ Wo^T -----------------------------
__global__ __launch_bounds__(256) void gemm_wo_kernel(
    const float* __restrict__ A, const float* __restrict__ B, float* __restrict__ C)
{
    extern __shared__ float sm[];
    gemm128_body(A, B, C, nullptr, 0, blockIdx.y * 128, blockIdx.x * 128, sm);
}

// =============================================================================
// Fused attention: per block = (32 i-rows, 1 head).
//   S = (Q/8) @ K^T + z  (full 1024-j row in smem)  -> softmax -> O = P@V
//   epilogue: o *= g (gate), write to g_o.
// Dynamic smem floats: S 32*1032 + Qs 32*68 + KVs 64*68 = 39552 (158208 B)
// =============================================================================
#define ATT_SMEM_BYTES 158208

__global__ __launch_bounds__(256) void fused_attn_kernel(
    const float* __restrict__ q, const float* __restrict__ k,
    const float* __restrict__ v, const float* __restrict__ gate,
    const float* __restrict__ z, float* __restrict__ o)
{
    extern __shared__ float sm[];
    float* S   = sm;                    // [32][1032]
    float* Qs  = sm + 32 * 1032;        // [32][68]
    float* KVs = Qs + 32 * 68;          // [64][68]

    const int t    = threadIdx.x;
    const int w    = t >> 5;
    const int lane = t & 31;
    const int h    = blockIdx.y;
    const int i0   = blockIdx.x * 32;

    // load Q tile, pre-scaled by 1/8 (exact power of 2)
    {
        int r = t >> 3, c = (t & 7) * 8;
        const float* src = q + (long)(i0 + r) * CS + h * HD + c;
        float4 a = *(const float4*)src;
        float4 b = *(const float4*)(src + 4);
        a.x *= 0.125f; a.y *= 0.125f; a.z *= 0.125f; a.w *= 0.125f;
        b.x *= 0.125f; b.y *= 0.125f; b.z *= 0.125f; b.w *= 0.125f;
        *(float4*)&Qs[r * 68 + c]     = a;
        *(float4*)&Qs[r * 68 + c + 4] = b;
    }
    __syncthreads();

    // ---------- phase 1: S = (Q/8) @ K^T ------------------------------------
    const int wm = w >> 2;   // 0..1
    const int wn = w & 3;    // 0..3
    for (int jt = 0; jt < 16; jt++) {
        int j0 = jt * 64;
        {   // load K tile 64x64
            int r = t >> 2; int cb = (t & 3) * 16;
            const float* src = k + (long)(j0 + r) * CS + h * HD + cb;
#pragma unroll
            for (int i = 0; i < 4; i++)
                *(float4*)&KVs[r * 68 + cb + i * 4] = *(const float4*)(src + i * 4);
        }
        __syncthreads();

        wmma::fragment<wmma::accumulator, 16, 16, 8, float> sacc;
        wmma::fill_fragment(sacc, 0.f);
#pragma unroll
        for (int kk = 0; kk < 64; kk += 8) {
            wmma::fragment<wmma::matrix_a, 16, 16, 8, wmma::precision::tf32, wmma::row_major> af;
            wmma::fragment<wmma::matrix_b, 16, 16, 8, wmma::precision::tf32, wmma::col_major> bf;
            wmma::load_matrix_sync(af, &Qs[(wm * 16) * 68 + kk], 68);
            wmma::load_matrix_sync(bf, &KVs[(wn * 16) * 68 + kk], 68);
#pragma unroll
            for (int e = 0; e < af.num_elements; e++) af.x[e] = wmma::__float_to_tf32(af.x[e]);
#pragma unroll
            for (int e = 0; e < bf.num_elements; e++) bf.x[e] = wmma::__float_to_tf32(bf.x[e]);
            wmma::mma_sync(sacc, af, bf, sacc);
        }
        wmma::store_matrix_sync(&S[(wm * 16) * 1032 + j0 + wn * 16], sacc, 1032,
                                wmma::mem_row_major);
        __syncthreads();
    }

    // ---------- phase 2: softmax rows with fused z add ----------------------
    // warp w owns rows w*4 .. w*4+3
#pragma unroll
    for (int rr = 0; rr < 4; rr++) {
        int r = w * 4 + rr;
        float* srow = S + r * 1032;
        const float* zrow = z + ((size_t)h * SEQ + i0 + r) * SEQ;

        float4 vv[8];
        float mx = -1e30f;
#pragma unroll
        for (int c = 0; c < 8; c++) {
            int col = c * 128 + lane * 4;
            float4 sv = *(float4*)&srow[col];
            float4 zv = *(const float4*)&zrow[col];
            sv.x += zv.x; sv.y += zv.y; sv.z += zv.z; sv.w += zv.w;
            vv[c] = sv;
            mx = fmaxf(mx, fmaxf(fmaxf(sv.x, sv.y), fmaxf(sv.z, sv.w)));
        }
#pragma unroll
        for (int o2 = 16; o2 > 0; o2 >>= 1)
            mx = fmaxf(mx, __shfl_xor_sync(0xffffffffu, mx, o2));

        float sum = 0.f;
#pragma unroll
        for (int c = 0; c < 8; c++) {
            vv[c].x = __expf(vv[c].x - mx);
            vv[c].y = __expf(vv[c].y - mx);
            vv[c].z = __expf(vv[c].z - mx);
            vv[c].w = __expf(vv[c].w - mx);
            sum += vv[c].x + vv[c].y + vv[c].z + vv[c].w;
        }
#pragma unroll
        for (int o2 = 16; o2 > 0; o2 >>= 1)
            sum += __shfl_xor_sync(0xffffffffu, sum, o2);
        float inv = 1.0f / sum;

#pragma unroll
        for (int c = 0; c < 8; c++) {
            int col = c * 128 + lane * 4;
            vv[c].x *= inv; vv[c].y *= inv; vv[c].z *= inv; vv[c].w *= inv;
            *(float4*)&srow[col] = vv[c];
        }
    }

    // ---------- phase 3: O = P @ V ------------------------------------------
    wmma::fragment<wmma::accumulator, 16, 16, 8, float> oacc;
    wmma::fill_fragment(oacc, 0.f);
    for (int jt = 0; jt < 16; jt++) {
        int j0 = jt * 64;
        {   // load V tile 64x64
            int r = t >> 2; int cb = (t & 3) * 16;
            const float* src = v + (long)(j0 + r) * CS + h * HD + cb;
#pragma unroll
            for (int i = 0; i < 4; i++)
                *(float4*)&KVs[r * 68 + cb + i * 4] = *(const float4*)(src + i * 4);
        }
        __syncthreads();   // also orders phase-2 S writes before P reads (jt=0)

#pragma unroll
        for (int kk = 0; kk < 64; kk += 8) {
            wmma::fragment<wmma::matrix_a, 16, 16, 8, wmma::precision::tf32, wmma::row_major> af;
            wmma::fragment<wmma::matrix_b, 16, 16, 8, wmma::precision::tf32, wmma::row_major> bf;
            wmma::load_matrix_sync(af, &S[(wm * 16) * 1032 + j0 + kk], 1032);
            wmma::load_matrix_sync(bf, &KVs[kk * 68 + wn * 16], 68);
#pragma unroll
            for (int e = 0; e < af.num_elements; e++) af.x[e] = wmma::__float_to_tf32(af.x[e]);
#pragma unroll
            for (int e = 0; e < bf.num_elements; e++) bf.x[e] = wmma::__float_to_tf32(bf.x[e]);
            wmma::mma_sync(oacc, af, bf, oacc);
        }
        __syncthreads();
    }

    // epilogue: stage O in Qs, gate with g, write
    wmma::store_matrix_sync(&Qs[(wm * 16) * 68 + wn * 16], oacc, 68, wmma::mem_row_major);
    __syncthreads();
    {
        int r = t >> 3, c = (t & 7) * 8;
        const float* gp = gate + (long)(i0 + r) * CS + h * HD + c;
        float*       op = o    + (long)(i0 + r) * CS + h * HD + c;
        float4 o0 = *(float4*)&Qs[r * 68 + c];
        float4 o1 = *(float4*)&Qs[r * 68 + c + 4];
        float4 g0 = *(const float4*)gp;
        float4 g1 = *(const float4*)(gp + 4);
        o0.x *= g0.x; o0.y *= g0.y; o0.z *= g0.z; o0.w *= g0.w;
        o1.x *= g1.x; o1.y *= g1.y; o1.z *= g1.z; o1.w *= g1.w;
        *(float4*)op       = o0;
        *(float4*)(op + 4) = o1;
    }
}

// ---------------- launcher ----------------------------------------------------
extern "C" void kernel_launch(void* const* d_in, const int* in_sizes, int n_in,
                              void* d_out, int out_size)
{
    const float* s    = (const float*)d_in[0];
    const float* k_in = (const float*)d_in[1];
    const float* mask = (const float*)d_in[2];
    const float* bias = (const float*)d_in[3];
    const float* Wq   = (const float*)d_in[4];
    const float* bq   = (const float*)d_in[5];
    const float* Wk   = (const float*)d_in[6];
    const float* Wv   = (const float*)d_in[7];
    const float* Wg   = (const float*)d_in[8];
    const float* Wo   = (const float*)d_in[9];
    const float* Wz   = (const float*)d_in[10];
    float* out = (float*)d_out;

    float *pq, *pk, *pv, *pg, *po, *patt;
    cudaGetSymbolAddress((void**)&pq,   g_q);
    cudaGetSymbolAddress((void**)&pk,   g_k);
    cudaGetSymbolAddress((void**)&pv,   g_v);
    cudaGetSymbolAddress((void**)&pg,   g_g);
    cudaGetSymbolAddress((void**)&po,   g_o);
    cudaGetSymbolAddress((void**)&patt, g_att);

    // unconditional (no static guards allowed); cheap + idempotent + capture-safe
    cudaFuncSetAttribute(stage1_kernel,
        cudaFuncAttributeMaxDynamicSharedMemorySize, GEMM_SMEM_BYTES);
    cudaFuncSetAttribute(gemm_wo_kernel,
        cudaFuncAttributeMaxDynamicSharedMemorySize, GEMM_SMEM_BYTES);
    cudaFuncSetAttribute(fused_attn_kernel,
        cudaFuncAttributeMaxDynamicSharedMemorySize, ATT_SMEM_BYTES);

    dim3 blk(256);

    // stage1: q,k,v,g projections (256 tensor blocks) + zbias (1024 HBM blocks)
    stage1_kernel<<<1280, blk, GEMM_SMEM_BYTES>>>(
        s, k_in, Wq, bq, Wk, Wv, Wg, pq, pk, pv, pg,
        bias, Wz, mask, patt);

    // fused attention: S=QK/8+z, softmax, O=PV, gate by g -> po
    fused_attn_kernel<<<dim3(32, NH), blk, ATT_SMEM_BYTES>>>(
        pq, pk, pv, pg, patt, po);

    // out = (g .* o) @ Wo^T
    gemm_wo_kernel<<<dim3(8, 8), blk, GEMM_SMEM_BYTES>>>(po, Wo, out);
}

// round 10
// speedup vs baseline: 1.0024x; 1.0024x over previous
#include <cuda_runtime.h>
#include <mma.h>
#include <math.h>
#include <stdint.h>

using namespace nvcuda;

#define SEQ 1024
#define CS  1024
#define NH  16
#define HD  64
#define CZ  128

// ---------------- scratch (device globals; no allocation allowed) -------------
__device__ float g_q[SEQ * CS];
__device__ float g_k[SEQ * CS];
__device__ float g_v[SEQ * CS];
__device__ float g_g[SEQ * CS];
__device__ float g_o[SEQ * CS];   // gated o (input to Wo gemm)
__device__ float g_att[(size_t)NH * SEQ * SEQ];   // z (pair bias + mask), 64 MB

// ---------------- cp.async helpers -------------------------------------------
__device__ __forceinline__ uint32_t sptr(const void* p) {
    return (uint32_t)__cvta_generic_to_shared(p);
}
#define CP_ASYNC16(dst, src) \
    asm volatile("cp.async.cg.shared.global [%0], [%1], 16;\n" :: "r"(dst), "l"(src))
#define CP_COMMIT() asm volatile("cp.async.commit_group;\n" ::)
#define CP_WAIT(N)  asm volatile("cp.async.wait_group %0;\n" :: "n"(N))

// =============================================================================
// NT TF32 GEMM body: C[m,n] = sum_k A[m,k]*B[n,k], M=N=K=1024 fixed.
// 128x128 block tile, BK=32, 256 threads, warp tile 32x64, double-buffered
// cp.async. mode 0: plain  1: +bias[n]  2: sigmoid
// Dynamic smem: 2*(128*36)*2 floats = 73728 B  (epilogue reuses as Cs 128x132)
// =============================================================================
#define GEMM_SMEM_BYTES 73728

__device__ __forceinline__ void gemm128_body(
    const float* __restrict__ A, const float* __restrict__ B,
    float* __restrict__ C, const float* __restrict__ bias, int mode,
    int m0, int n0, float* sm)
{
    const int t = threadIdx.x;
    const int w = t >> 5;
    const int m_base = (w >> 1) * 32;   // warp_m 0..3
    const int n_base = (w & 1) * 64;    // warp_n 0..1

    float* As = sm;                 // [2][128][36]
    float* Bs = sm + 2 * 128 * 36;  // [2][128][36]

    const int lrow = t >> 1;               // 0..127
    const int lcol = (t & 1) * 16;         // 0 or 16

    wmma::fragment<wmma::accumulator, 16, 16, 8, float> acc[2][4];
#pragma unroll
    for (int i = 0; i < 2; i++)
#pragma unroll
        for (int j = 0; j < 4; j++) wmma::fill_fragment(acc[i][j], 0.f);

    // prologue: load k-tile 0 into buf 0
    {
        const float* arow = A + (long)(m0 + lrow) * CS + lcol;
        const float* brow = B + (long)(n0 + lrow) * CS + lcol;
        uint32_t da = sptr(&As[lrow * 36 + lcol]);
        uint32_t db = sptr(&Bs[lrow * 36 + lcol]);
#pragma unroll
        for (int i = 0; i < 4; i++) {
            CP_ASYNC16(da + i * 16, arow + i * 4);
            CP_ASYNC16(db + i * 16, brow + i * 4);
        }
        CP_COMMIT();
    }

    const int KT = CS / 32;
    int buf = 0;
    for (int kt = 0; kt < KT; kt++) {
        if (kt + 1 < KT) {
            int nb = buf ^ 1;
            int k0 = (kt + 1) * 32;
            const float* arow = A + (long)(m0 + lrow) * CS + k0 + lcol;
            const float* brow = B + (long)(n0 + lrow) * CS + k0 + lcol;
            uint32_t da = sptr(&As[nb * 4608 + lrow * 36 + lcol]);
            uint32_t db = sptr(&Bs[nb * 4608 + lrow * 36 + lcol]);
#pragma unroll
            for (int i = 0; i < 4; i++) {
                CP_ASYNC16(da + i * 16, arow + i * 4);
                CP_ASYNC16(db + i * 16, brow + i * 4);
            }
            CP_COMMIT();
            CP_WAIT(1);
        } else {
            CP_WAIT(0);
        }
        __syncthreads();

        const float* Ab = As + buf * 4608;
        const float* Bb = Bs + buf * 4608;
#pragma unroll
        for (int kk = 0; kk < 32; kk += 8) {
            wmma::fragment<wmma::matrix_a, 16, 16, 8, wmma::precision::tf32, wmma::row_major> af[2];
            wmma::fragment<wmma::matrix_b, 16, 16, 8, wmma::precision::tf32, wmma::col_major> bf[4];
#pragma unroll
            for (int i = 0; i < 2; i++) {
                wmma::load_matrix_sync(af[i], &Ab[(m_base + 16 * i) * 36 + kk], 36);
#pragma unroll
                for (int e = 0; e < af[i].num_elements; e++)
                    af[i].x[e] = wmma::__float_to_tf32(af[i].x[e]);
            }
#pragma unroll
            for (int j = 0; j < 4; j++) {
                wmma::load_matrix_sync(bf[j], &Bb[(n_base + 16 * j) * 36 + kk], 36);
#pragma unroll
                for (int e = 0; e < bf[j].num_elements; e++)
                    bf[j].x[e] = wmma::__float_to_tf32(bf[j].x[e]);
            }
#pragma unroll
            for (int i = 0; i < 2; i++)
#pragma unroll
                for (int j = 0; j < 4; j++)
                    wmma::mma_sync(acc[i][j], af[i], bf[j], acc[i][j]);
        }
        __syncthreads();
        buf ^= 1;
    }

    // epilogue: stage through smem (reuse as Cs[128][132])
#pragma unroll
    for (int i = 0; i < 2; i++)
#pragma unroll
        for (int j = 0; j < 4; j++)
            wmma::store_matrix_sync(&sm[(m_base + 16 * i) * 132 + n_base + 16 * j],
                                    acc[i][j], 132, wmma::mem_row_major);
    __syncthreads();

    {
        int r = t >> 1;                    // 0..127
        int cbase = (t & 1) * 64;
        long crow = (long)(m0 + r) * CS + n0;
#pragma unroll
        for (int i = 0; i < 16; i++) {
            int c = cbase + i * 4;
            float4 v = *(float4*)&sm[r * 132 + c];
            if (mode == 1) {
                float4 b4 = *(const float4*)&bias[n0 + c];
                v.x += b4.x; v.y += b4.y; v.z += b4.z; v.w += b4.w;
            } else if (mode == 2) {
                v.x = 1.f / (1.f + __expf(-v.x));
                v.y = 1.f / (1.f + __expf(-v.y));
                v.z = 1.f / (1.f + __expf(-v.z));
                v.w = 1.f / (1.f + __expf(-v.w));
            }
            *(float4*)&C[crow + c] = v;
        }
    }
}

// ---------------- proj4: q,k,v,g projections (standalone, reg-capped) ---------
__global__ __launch_bounds__(256, 2) void proj4_kernel(
    const float* __restrict__ s, const float* __restrict__ k_in,
    const float* __restrict__ Wq, const float* __restrict__ bq,
    const float* __restrict__ Wk, const float* __restrict__ Wv,
    const float* __restrict__ Wg,
    float* __restrict__ q, float* __restrict__ k,
    float* __restrict__ v, float* __restrict__ g)
{
    extern __shared__ float sm[];
    int z   = blockIdx.z;
    int m0  = blockIdx.y * 128;
    int n0  = blockIdx.x * 128;
    const float* A = (z == 0 || z == 3) ? s : k_in;
    const float* W = (z == 0) ? Wq : (z == 1) ? Wk : (z == 2) ? Wv : Wg;
    float*       C = (z == 0) ? q  : (z == 1) ? k  : (z == 2) ? v  : g;
    int mode       = (z == 0) ? 1  : (z == 3) ? 2  : 0;
    gemm128_body(A, W, C, bq, mode, m0, n0, sm);
}

// ---------------- zbias: standalone (low regs, small static smem) -------------
__global__ __launch_bounds__(256) void zbias_kernel(
    const float* __restrict__ bias, const float* __restrict__ Wz,
    const float* __restrict__ mask, float* __restrict__ zout)
{
    __shared__ float wz[CZ * NH];
    int t = threadIdx.x;
    for (int idx = t; idx < CZ * NH; idx += 256) wz[idx] = Wz[idx];
    __syncthreads();

    int i = blockIdx.x;
    const float* bp = bias + (size_t)i * SEQ * CZ;

    float acc[4][NH];
#pragma unroll
    for (int p = 0; p < 4; p++)
#pragma unroll
        for (int h = 0; h < NH; h++) acc[p][h] = 0.f;

#pragma unroll 1
    for (int c4 = 0; c4 < CZ / 4; c4++) {
        float bvf[4][4];
#pragma unroll
        for (int p = 0; p < 4; p++) {
            float4 bv = *(const float4*)(bp + (size_t)(t + p * 256) * CZ + c4 * 4);
            bvf[p][0] = bv.x; bvf[p][1] = bv.y; bvf[p][2] = bv.z; bvf[p][3] = bv.w;
        }
#pragma unroll
        for (int cc = 0; cc < 4; cc++) {
            int c = c4 * 4 + cc;
            float4 w0 = *(const float4*)&wz[c * NH + 0];
            float4 w1 = *(const float4*)&wz[c * NH + 4];
            float4 w2 = *(const float4*)&wz[c * NH + 8];
            float4 w3 = *(const float4*)&wz[c * NH + 12];
#pragma unroll
            for (int p = 0; p < 4; p++) {
                float b = bvf[p][cc];
                acc[p][0]  += b * w0.x; acc[p][1]  += b * w0.y; acc[p][2]  += b * w0.z; acc[p][3]  += b * w0.w;
                acc[p][4]  += b * w1.x; acc[p][5]  += b * w1.y; acc[p][6]  += b * w1.z; acc[p][7]  += b * w1.w;
                acc[p][8]  += b * w2.x; acc[p][9]  += b * w2.y; acc[p][10] += b * w2.z; acc[p][11] += b * w2.w;
                acc[p][12] += b * w3.x; acc[p][13] += b * w3.y; acc[p][14] += b * w3.z; acc[p][15] += b * w3.w;
            }
        }
    }

    float mk[4];
#pragma unroll
    for (int p = 0; p < 4; p++)
        mk[p] = (1.0f - mask[t + p * 256]) * (-1000000.0f);

#pragma unroll
    for (int h = 0; h < NH; h++) {
        float* row = zout + ((size_t)h * SEQ + i) * SEQ;
#pragma unroll
        for (int p = 0; p < 4; p++)
            row[t + p * 256] = acc[p][h] + mk[p];
    }
}

// ---------------- Wo GEMM: out = (gated o) @ Wo^T -----------------------------
__global__ __launch_bounds__(256, 2) void gemm_wo_kernel(
    const float* __restrict__ A, const float* __restrict__ B, float* __restrict__ C)
{
    extern __shared__ float sm[];
    gemm128_body(A, B, C, nullptr, 0, blockIdx.y * 128, blockIdx.x * 128, sm);
}

// =============================================================================
// Fused attention: per block = (32 i-rows, 1 head).
//   S = (Q/8) @ K^T + z  (full 1024-j row in smem)  -> softmax -> O = P@V
//   epilogue: o *= g (gate), write to g_o.
// Dynamic smem floats: S 32*1032 + Qs 32*68 + KVs 64*68 = 39552 (158208 B)
// =============================================================================
#define ATT_SMEM_BYTES 158208

__global__ __launch_bounds__(256) void fused_attn_kernel(
    const float* __restrict__ q, const float* __restrict__ k,
    const float* __restrict__ v, const float* __restrict__ gate,
    const float* __restrict__ z, float* __restrict__ o)
{
    extern __shared__ float sm[];
    float* S   = sm;                    // [32][1032]
    float* Qs  = sm + 32 * 1032;        // [32][68]
    float* KVs = Qs + 32 * 68;          // [64][68]

    const int t    = threadIdx.x;
    const int w    = t >> 5;
    const int lane = t & 31;
    const int h    = blockIdx.y;
    const int i0   = blockIdx.x * 32;

    // load Q tile, pre-scaled by 1/8 (exact power of 2)
    {
        int r = t >> 3, c = (t & 7) * 8;
        const float* src = q + (long)(i0 + r) * CS + h * HD + c;
        float4 a = *(const float4*)src;
        float4 b = *(const float4*)(src + 4);
        a.x *= 0.125f; a.y *= 0.125f; a.z *= 0.125f; a.w *= 0.125f;
        b.x *= 0.125f; b.y *= 0.125f; b.z *= 0.125f; b.w *= 0.125f;
        *(float4*)&Qs[r * 68 + c]     = a;
        *(float4*)&Qs[r * 68 + c + 4] = b;
    }
    __syncthreads();

    // ---------- phase 1: S = (Q/8) @ K^T ------------------------------------
    const int wm = w >> 2;   // 0..1
    const int wn = w & 3;    // 0..3
    for (int jt = 0; jt < 16; jt++) {
        int j0 = jt * 64;
        {   // load K tile 64x64
            int r = t >> 2; int cb = (t & 3) * 16;
            const float* src = k + (long)(j0 + r) * CS + h * HD + cb;
#pragma unroll
            for (int i = 0; i < 4; i++)
                *(float4*)&KVs[r * 68 + cb + i * 4] = *(const float4*)(src + i * 4);
        }
        __syncthreads();

        wmma::fragment<wmma::accumulator, 16, 16, 8, float> sacc;
        wmma::fill_fragment(sacc, 0.f);
#pragma unroll
        for (int kk = 0; kk < 64; kk += 8) {
            wmma::fragment<wmma::matrix_a, 16, 16, 8, wmma::precision::tf32, wmma::row_major> af;
            wmma::fragment<wmma::matrix_b, 16, 16, 8, wmma::precision::tf32, wmma::col_major> bf;
            wmma::load_matrix_sync(af, &Qs[(wm * 16) * 68 + kk], 68);
            wmma::load_matrix_sync(bf, &KVs[(wn * 16) * 68 + kk], 68);
#pragma unroll
            for (int e = 0; e < af.num_elements; e++) af.x[e] = wmma::__float_to_tf32(af.x[e]);
#pragma unroll
            for (int e = 0; e < bf.num_elements; e++) bf.x[e] = wmma::__float_to_tf32(bf.x[e]);
            wmma::mma_sync(sacc, af, bf, sacc);
        }
        wmma::store_matrix_sync(&S[(wm * 16) * 1032 + j0 + wn * 16], sacc, 1032,
                                wmma::mem_row_major);
        __syncthreads();
    }

    // ---------- phase 2: softmax rows with fused z add ----------------------
    // warp w owns rows w*4 .. w*4+3
#pragma unroll
    for (int rr = 0; rr < 4; rr++) {
        int r = w * 4 + rr;
        float* srow = S + r * 1032;
        const float* zrow = z + ((size_t)h * SEQ + i0 + r) * SEQ;

        float4 vv[8];
        float mx = -1e30f;
#pragma unroll
        for (int c = 0; c < 8; c++) {
            int col = c * 128 + lane * 4;
            float4 sv = *(float4*)&srow[col];
            float4 zv = *(const float4*)&zrow[col];
            sv.x += zv.x; sv.y += zv.y; sv.z += zv.z; sv.w += zv.w;
            vv[c] = sv;
            mx = fmaxf(mx, fmaxf(fmaxf(sv.x, sv.y), fmaxf(sv.z, sv.w)));
        }
#pragma unroll
        for (int o2 = 16; o2 > 0; o2 >>= 1)
            mx = fmaxf(mx, __shfl_xor_sync(0xffffffffu, mx, o2));

        float sum = 0.f;
#pragma unroll
        for (int c = 0; c < 8; c++) {
            vv[c].x = __expf(vv[c].x - mx);
            vv[c].y = __expf(vv[c].y - mx);
            vv[c].z = __expf(vv[c].z - mx);
            vv[c].w = __expf(vv[c].w - mx);
            sum += vv[c].x + vv[c].y + vv[c].z + vv[c].w;
        }
#pragma unroll
        for (int o2 = 16; o2 > 0; o2 >>= 1)
            sum += __shfl_xor_sync(0xffffffffu, sum, o2);
        float inv = 1.0f / sum;

#pragma unroll
        for (int c = 0; c < 8; c++) {
            int col = c * 128 + lane * 4;
            vv[c].x *= inv; vv[c].y *= inv; vv[c].z *= inv; vv[c].w *= inv;
            *(float4*)&srow[col] = vv[c];
        }
    }

    // ---------- phase 3: O = P @ V ------------------------------------------
    wmma::fragment<wmma::accumulator, 16, 16, 8, float> oacc;
    wmma::fill_fragment(oacc, 0.f);
    for (int jt = 0; jt < 16; jt++) {
        int j0 = jt * 64;
        {   // load V tile 64x64
            int r = t >> 2; int cb = (t & 3) * 16;
            const float* src = v + (long)(j0 + r) * CS + h * HD + cb;
#pragma unroll
            for (int i = 0; i < 4; i++)
                *(float4*)&KVs[r * 68 + cb + i * 4] = *(const float4*)(src + i * 4);
        }
        __syncthreads();   // also orders phase-2 S writes before P reads (jt=0)

#pragma unroll
        for (int kk = 0; kk < 64; kk += 8) {
            wmma::fragment<wmma::matrix_a, 16, 16, 8, wmma::precision::tf32, wmma::row_major> af;
            wmma::fragment<wmma::matrix_b, 16, 16, 8, wmma::precision::tf32, wmma::row_major> bf;
            wmma::load_matrix_sync(af, &S[(wm * 16) * 1032 + j0 + kk], 1032);
            wmma::load_matrix_sync(bf, &KVs[kk * 68 + wn * 16], 68);
#pragma unroll
            for (int e = 0; e < af.num_elements; e++) af.x[e] = wmma::__float_to_tf32(af.x[e]);
#pragma unroll
            for (int e = 0; e < bf.num_elements; e++) bf.x[e] = wmma::__float_to_tf32(bf.x[e]);
            wmma::mma_sync(oacc, af, bf, oacc);
        }
        __syncthreads();
    }

    // epilogue: stage O in Qs, gate with g, write
    wmma::store_matrix_sync(&Qs[(wm * 16) * 68 + wn * 16], oacc, 68, wmma::mem_row_major);
    __syncthreads();
    {
        int r = t >> 3, c = (t & 7) * 8;
        const float* gp = gate + (long)(i0 + r) * CS + h * HD + c;
        float*       op = o    + (long)(i0 + r) * CS + h * HD + c;
        float4 o0 = *(float4*)&Qs[r * 68 + c];
        float4 o1 = *(float4*)&Qs[r * 68 + c + 4];
        float4 g0 = *(const float4*)gp;
        float4 g1 = *(const float4*)(gp + 4);
        o0.x *= g0.x; o0.y *= g0.y; o0.z *= g0.z; o0.w *= g0.w;
        o1.x *= g1.x; o1.y *= g1.y; o1.z *= g1.z; o1.w *= g1.w;
        *(float4*)op       = o0;
        *(float4*)(op + 4) = o1;
    }
}

// ---------------- launcher ----------------------------------------------------
extern "C" void kernel_launch(void* const* d_in, const int* in_sizes, int n_in,
                              void* d_out, int out_size)
{
    const float* s    = (const float*)d_in[0];
    const float* k_in = (const float*)d_in[1];
    const float* mask = (const float*)d_in[2];
    const float* bias = (const float*)d_in[3];
    const float* Wq   = (const float*)d_in[4];
    const float* bq   = (const float*)d_in[5];
    const float* Wk   = (const float*)d_in[6];
    const float* Wv   = (const float*)d_in[7];
    const float* Wg   = (const float*)d_in[8];
    const float* Wo   = (const float*)d_in[9];
    const float* Wz   = (const float*)d_in[10];
    float* out = (float*)d_out;

    float *pq, *pk, *pv, *pg, *po, *patt;
    cudaGetSymbolAddress((void**)&pq,   g_q);
    cudaGetSymbolAddress((void**)&pk,   g_k);
    cudaGetSymbolAddress((void**)&pv,   g_v);
    cudaGetSymbolAddress((void**)&pg,   g_g);
    cudaGetSymbolAddress((void**)&po,   g_o);
    cudaGetSymbolAddress((void**)&patt, g_att);

    // unconditional (no static guards allowed); cheap + idempotent + capture-safe
    cudaFuncSetAttribute(proj4_kernel,
        cudaFuncAttributeMaxDynamicSharedMemorySize, GEMM_SMEM_BYTES);
    cudaFuncSetAttribute(gemm_wo_kernel,
        cudaFuncAttributeMaxDynamicSharedMemorySize, GEMM_SMEM_BYTES);
    cudaFuncSetAttribute(fused_attn_kernel,
        cudaFuncAttributeMaxDynamicSharedMemorySize, ATT_SMEM_BYTES);

    dim3 blk(256);

    // zbias: 512 MB bias read, HBM-bound, high-occupancy standalone kernel
    zbias_kernel<<<SEQ, blk>>>(bias, Wz, mask, patt);

    // q,k,v,g projections: tensor-bound, 2 CTAs/SM
    proj4_kernel<<<dim3(8, 8, 4), blk, GEMM_SMEM_BYTES>>>(
        s, k_in, Wq, bq, Wk, Wv, Wg, pq, pk, pv, pg);

    // fused attention: S=QK/8+z, softmax, O=PV, gate by g -> po
    fused_attn_kernel<<<dim3(32, NH), blk, ATT_SMEM_BYTES>>>(
        pq, pk, pv, pg, patt, po);

    // out = (g .* o) @ Wo^T
    gemm_wo_kernel<<<dim3(8, 8), blk, GEMM_SMEM_BYTES>>>(po, Wo, out);
}

// round 14
// speedup vs baseline: 1.1156x; 1.1129x over previous
#include <cuda_runtime.h>
#include <mma.h>
#include <math.h>
#include <stdint.h>

using namespace nvcuda;

#define SEQ 1024
#define CS  1024
#define NH  16
#define HD  64
#define CZ  128

// ---------------- scratch (device globals; no allocation allowed) -------------
__device__ float g_q[SEQ * CS];
__device__ float g_k[SEQ * CS];
__device__ float g_v[SEQ * CS];
__device__ float g_g[SEQ * CS];
__device__ float g_o[SEQ * CS];   // gated o (input to Wo gemm)
__device__ float g_att[(size_t)NH * SEQ * SEQ];   // z (pair bias + mask), 64 MB

// ---------------- cp.async helpers -------------------------------------------
__device__ __forceinline__ uint32_t sptr(const void* p) {
    return (uint32_t)__cvta_generic_to_shared(p);
}
#define CP_ASYNC16(dst, src) \
    asm volatile("cp.async.cg.shared.global [%0], [%1], 16;\n" :: "r"(dst), "l"(src))
#define CP_COMMIT() asm volatile("cp.async.commit_group;\n" ::)
#define CP_WAIT(N)  asm volatile("cp.async.wait_group %0;\n" :: "n"(N))

// =============================================================================
// NT TF32 GEMM body: C[m,n] = sum_k A[m,k]*B[n,k], K=1024 fixed.
// 64x128 block tile -> more blocks per GEMM (fills 148 SMs), 256 threads,
// warp tile 32x32 (warps 2x4), double-buffered cp.async.
// mode 0: plain  1: +bias[n]  2: sigmoid
// smem: As[2][64][36] + Bs[2][128][36] = 13824 floats = 55296 B
// =============================================================================
#define GEMM_SMEM_BYTES 55296

__device__ __forceinline__ void gemm64x128_body(
    const float* __restrict__ A, const float* __restrict__ B,
    float* __restrict__ C, const float* __restrict__ bias, int mode,
    int m0, int n0, float* sm)
{
    const int t = threadIdx.x;
    const int w = t >> 5;
    const int m_base = (w >> 2) * 32;   // wm 0..1
    const int n_base = (w & 3) * 32;    // wn 0..3

    float* As = sm;                 // [2][64][36]
    float* Bs = sm + 2 * 64 * 36;   // [2][128][36]

    const int arow_l = t >> 2;
    const int acol_l = (t & 3) * 8;
    const int brow_l = t >> 1;
    const int bcol_l = (t & 1) * 16;

    wmma::fragment<wmma::accumulator, 16, 16, 8, float> acc[2][2];
#pragma unroll
    for (int i = 0; i < 2; i++)
#pragma unroll
        for (int j = 0; j < 2; j++) wmma::fill_fragment(acc[i][j], 0.f);

    // prologue: k-tile 0 into buf 0
    {
        const float* ap = A + (long)(m0 + arow_l) * CS + acol_l;
        uint32_t da = sptr(&As[arow_l * 36 + acol_l]);
        CP_ASYNC16(da,      ap);
        CP_ASYNC16(da + 16, ap + 4);
        const float* bp = B + (long)(n0 + brow_l) * CS + bcol_l;
        uint32_t db = sptr(&Bs[brow_l * 36 + bcol_l]);
#pragma unroll
        for (int i = 0; i < 4; i++) CP_ASYNC16(db + i * 16, bp + i * 4);
        CP_COMMIT();
    }

    const int KT = CS / 32;
    int buf = 0;
    for (int kt = 0; kt < KT; kt++) {
        if (kt + 1 < KT) {
            int nb = buf ^ 1;
            int k0 = (kt + 1) * 32;
            const float* ap = A + (long)(m0 + arow_l) * CS + k0 + acol_l;
            uint32_t da = sptr(&As[nb * 2304 + arow_l * 36 + acol_l]);
            CP_ASYNC16(da,      ap);
            CP_ASYNC16(da + 16, ap + 4);
            const float* bp = B + (long)(n0 + brow_l) * CS + k0 + bcol_l;
            uint32_t db = sptr(&Bs[nb * 4608 + brow_l * 36 + bcol_l]);
#pragma unroll
            for (int i = 0; i < 4; i++) CP_ASYNC16(db + i * 16, bp + i * 4);
            CP_COMMIT();
            CP_WAIT(1);
        } else {
            CP_WAIT(0);
        }
        __syncthreads();

        const float* Ab = As + buf * 2304;
        const float* Bb = Bs + buf * 4608;
#pragma unroll
        for (int kk = 0; kk < 32; kk += 8) {
            wmma::fragment<wmma::matrix_a, 16, 16, 8, wmma::precision::tf32, wmma::row_major> af[2];
            wmma::fragment<wmma::matrix_b, 16, 16, 8, wmma::precision::tf32, wmma::col_major> bf[2];
#pragma unroll
            for (int i = 0; i < 2; i++) {
                wmma::load_matrix_sync(af[i], &Ab[(m_base + 16 * i) * 36 + kk], 36);
#pragma unroll
                for (int e = 0; e < af[i].num_elements; e++)
                    af[i].x[e] = wmma::__float_to_tf32(af[i].x[e]);
            }
#pragma unroll
            for (int j = 0; j < 2; j++) {
                wmma::load_matrix_sync(bf[j], &Bb[(n_base + 16 * j) * 36 + kk], 36);
#pragma unroll
                for (int e = 0; e < bf[j].num_elements; e++)
                    bf[j].x[e] = wmma::__float_to_tf32(bf[j].x[e]);
            }
#pragma unroll
            for (int i = 0; i < 2; i++)
#pragma unroll
                for (int j = 0; j < 2; j++)
                    wmma::mma_sync(acc[i][j], af[i], bf[j], acc[i][j]);
        }
        __syncthreads();
        buf ^= 1;
    }

    // epilogue: stage through smem (reuse as Cs[64][132] = 8448 floats)
#pragma unroll
    for (int i = 0; i < 2; i++)
#pragma unroll
        for (int j = 0; j < 2; j++)
            wmma::store_matrix_sync(&sm[(m_base + 16 * i) * 132 + n_base + 16 * j],
                                    acc[i][j], 132, wmma::mem_row_major);
    __syncthreads();

    {
        int r = t >> 2;                    // 0..63
        int cbase = (t & 3) * 32;          // 0,32,64,96
        long crow = (long)(m0 + r) * CS + n0;
#pragma unroll
        for (int i = 0; i < 8; i++) {
            int c = cbase + i * 4;
            float4 v = *(float4*)&sm[r * 132 + c];
            if (mode == 1) {
                float4 b4 = *(const float4*)&bias[n0 + c];
                v.x += b4.x; v.y += b4.y; v.z += b4.z; v.w += b4.w;
            } else if (mode == 2) {
                v.x = 1.f / (1.f + __expf(-v.x));
                v.y = 1.f / (1.f + __expf(-v.y));
                v.z = 1.f / (1.f + __expf(-v.z));
                v.w = 1.f / (1.f + __expf(-v.w));
            }
            *(float4*)&C[crow + c] = v;
        }
    }
}

// ---------------- proj4: q,k,v,g projections (512 blocks, 2 CTA/SM) -----------
__global__ __launch_bounds__(256, 2) void proj4_kernel(
    const float* __restrict__ s, const float* __restrict__ k_in,
    const float* __restrict__ Wq, const float* __restrict__ bq,
    const float* __restrict__ Wk, const float* __restrict__ Wv,
    const float* __restrict__ Wg,
    float* __restrict__ q, float* __restrict__ k,
    float* __restrict__ v, float* __restrict__ g)
{
    extern __shared__ float sm[];
    int z   = blockIdx.z;
    int m0  = blockIdx.y * 64;
    int n0  = blockIdx.x * 128;
    const float* A = (z == 0 || z == 3) ? s : k_in;
    const float* W = (z == 0) ? Wq : (z == 1) ? Wk : (z == 2) ? Wv : Wg;
    float*       C = (z == 0) ? q  : (z == 1) ? k  : (z == 2) ? v  : g;
    int mode       = (z == 0) ? 1  : (z == 3) ? 2  : 0;
    gemm64x128_body(A, W, C, bq, mode, m0, n0, sm);
}

// ---------------- Wo GEMM: out = (gated o) @ Wo^T  (128 blocks) ---------------
__global__ __launch_bounds__(256, 2) void gemm_wo_kernel(
    const float* __restrict__ A, const float* __restrict__ B, float* __restrict__ C)
{
    extern __shared__ float sm[];
    gemm64x128_body(A, B, C, nullptr, 0, blockIdx.y * 64, blockIdx.x * 128, sm);
}

// ---------------- zbias: standalone (low regs, small static smem) -------------
__global__ __launch_bounds__(256) void zbias_kernel(
    const float* __restrict__ bias, const float* __restrict__ Wz,
    const float* __restrict__ mask, float* __restrict__ zout)
{
    __shared__ float wz[CZ * NH];
    int t = threadIdx.x;
    for (int idx = t; idx < CZ * NH; idx += 256) wz[idx] = Wz[idx];
    __syncthreads();

    int i = blockIdx.x;
    const float* bp = bias + (size_t)i * SEQ * CZ;

    float acc[4][NH];
#pragma unroll
    for (int p = 0; p < 4; p++)
#pragma unroll
        for (int h = 0; h < NH; h++) acc[p][h] = 0.f;

#pragma unroll 1
    for (int c4 = 0; c4 < CZ / 4; c4++) {
        float bvf[4][4];
#pragma unroll
        for (int p = 0; p < 4; p++) {
            float4 bv = *(const float4*)(bp + (size_t)(t + p * 256) * CZ + c4 * 4);
            bvf[p][0] = bv.x; bvf[p][1] = bv.y; bvf[p][2] = bv.z; bvf[p][3] = bv.w;
        }
#pragma unroll
        for (int cc = 0; cc < 4; cc++) {
            int c = c4 * 4 + cc;
            float4 w0 = *(const float4*)&wz[c * NH + 0];
            float4 w1 = *(const float4*)&wz[c * NH + 4];
            float4 w2 = *(const float4*)&wz[c * NH + 8];
            float4 w3 = *(const float4*)&wz[c * NH + 12];
#pragma unroll
            for (int p = 0; p < 4; p++) {
                float b = bvf[p][cc];
                acc[p][0]  += b * w0.x; acc[p][1]  += b * w0.y; acc[p][2]  += b * w0.z; acc[p][3]  += b * w0.w;
                acc[p][4]  += b * w1.x; acc[p][5]  += b * w1.y; acc[p][6]  += b * w1.z; acc[p][7]  += b * w1.w;
                acc[p][8]  += b * w2.x; acc[p][9]  += b * w2.y; acc[p][10] += b * w2.z; acc[p][11] += b * w2.w;
                acc[p][12] += b * w3.x; acc[p][13] += b * w3.y; acc[p][14] += b * w3.z; acc[p][15] += b * w3.w;
            }
        }
    }

    float mk[4];
#pragma unroll
    for (int p = 0; p < 4; p++)
        mk[p] = (1.0f - mask[t + p * 256]) * (-1000000.0f);

#pragma unroll
    for (int h = 0; h < NH; h++) {
        float* row = zout + ((size_t)h * SEQ + i) * SEQ;
#pragma unroll
        for (int p = 0; p < 4; p++)
            row[t + p * 256] = acc[p][h] + mk[p];
    }
}

// =============================================================================
// Fused attention: per block = (32 i-rows, 1 head).
//   S = (Q/8) @ K^T + z -> softmax -> O = P@V, gate by g.
//   K/V tiles double-buffered via cp.async (loads were fully exposed before).
// smem floats: S 32*1032 + Qs 32*68 + KVs 2*64*68 = 43904 (175616 B)
// =============================================================================
#define ATT_SMEM_BYTES 175616

__global__ __launch_bounds__(256) void fused_attn_kernel(
    const float* __restrict__ q, const float* __restrict__ k,
    const float* __restrict__ v, const float* __restrict__ gate,
    const float* __restrict__ z, float* __restrict__ o)
{
    extern __shared__ float sm[];
    float* S   = sm;                    // [32][1032]
    float* Qs  = sm + 32 * 1032;        // [32][68]
    float* KVs = Qs + 32 * 68;          // [2][64][68]

    const int t    = threadIdx.x;
    const int w    = t >> 5;
    const int lane = t & 31;
    const int h    = blockIdx.y;
    const int i0   = blockIdx.x * 32;

    const int kvrow = t >> 2;
    const int kvcol = (t & 3) * 16;
    const float* kbase = k + (long)kvrow * CS + h * HD + kvcol;
    const float* vbase = v + (long)kvrow * CS + h * HD + kvcol;

    // load Q tile, pre-scaled by 1/8 (exact power of 2)
    {
        int r = t >> 3, c = (t & 7) * 8;
        const float* src = q + (long)(i0 + r) * CS + h * HD + c;
        float4 a = *(const float4*)src;
        float4 b = *(const float4*)(src + 4);
        a.x *= 0.125f; a.y *= 0.125f; a.z *= 0.125f; a.w *= 0.125f;
        b.x *= 0.125f; b.y *= 0.125f; b.z *= 0.125f; b.w *= 0.125f;
        *(float4*)&Qs[r * 68 + c]     = a;
        *(float4*)&Qs[r * 68 + c + 4] = b;
    }

    // ---------- phase 1: S = (Q/8) @ K^T, cp.async double-buffered K ---------
    const int wm = w >> 2;   // 0..1
    const int wn = w & 3;    // 0..3
    {   // prologue: K tile 0 -> buf 0
        uint32_t d = sptr(&KVs[kvrow * 68 + kvcol]);
#pragma unroll
        for (int i = 0; i < 4; i++) CP_ASYNC16(d + i * 16, kbase + i * 4);
        CP_COMMIT();
    }
    int buf = 0;
    for (int jt = 0; jt < 16; jt++) {
        if (jt + 1 < 16) {
            int nb = buf ^ 1;
            uint32_t d = sptr(&KVs[nb * 4352 + kvrow * 68 + kvcol]);
            const float* src = kbase + (long)(jt + 1) * 64 * CS;
#pragma unroll
            for (int i = 0; i < 4; i++) CP_ASYNC16(d + i * 16, src + i * 4);
            CP_COMMIT();
            CP_WAIT(1);
        } else {
            CP_WAIT(0);
        }
        __syncthreads();   // K tile visible block-wide (also covers Qs at jt=0)

        const float* Kb = KVs + buf * 4352;
        wmma::fragment<wmma::accumulator, 16, 16, 8, float> sacc;
        wmma::fill_fragment(sacc, 0.f);
#pragma unroll
        for (int kk = 0; kk < 64; kk += 8) {
            wmma::fragment<wmma::matrix_a, 16, 16, 8, wmma::precision::tf32, wmma::row_major> af;
            wmma::fragment<wmma::matrix_b, 16, 16, 8, wmma::precision::tf32, wmma::col_major> bf;
            wmma::load_matrix_sync(af, &Qs[(wm * 16) * 68 + kk], 68);
            wmma::load_matrix_sync(bf, &Kb[(wn * 16) * 68 + kk], 68);
#pragma unroll
            for (int e = 0; e < af.num_elements; e++) af.x[e] = wmma::__float_to_tf32(af.x[e]);
#pragma unroll
            for (int e = 0; e < bf.num_elements; e++) bf.x[e] = wmma::__float_to_tf32(bf.x[e]);
            wmma::mma_sync(sacc, af, bf, sacc);
        }
        wmma::store_matrix_sync(&S[(wm * 16) * 1032 + jt * 64 + wn * 16], sacc, 1032,
                                wmma::mem_row_major);
        __syncthreads();   // all reads of buf done before it is overwritten
        buf ^= 1;
    }

    // prefetch V tile 0 into buf 0 — latency hidden under softmax
    {
        uint32_t d = sptr(&KVs[kvrow * 68 + kvcol]);
#pragma unroll
        for (int i = 0; i < 4; i++) CP_ASYNC16(d + i * 16, vbase + i * 4);
        CP_COMMIT();
    }

    // ---------- phase 2: softmax rows with fused z add ----------------------
#pragma unroll
    for (int rr = 0; rr < 4; rr++) {
        int r = w * 4 + rr;
        float* srow = S + r * 1032;
        const float* zrow = z + ((size_t)h * SEQ + i0 + r) * SEQ;

        float4 vv[8];
        float mx = -1e30f;
#pragma unroll
        for (int c = 0; c < 8; c++) {
            int col = c * 128 + lane * 4;
            float4 sv = *(float4*)&srow[col];
            float4 zv = *(const float4*)&zrow[col];
            sv.x += zv.x; sv.y += zv.y; sv.z += zv.z; sv.w += zv.w;
            vv[c] = sv;
            mx = fmaxf(mx, fmaxf(fmaxf(sv.x, sv.y), fmaxf(sv.z, sv.w)));
        }
#pragma unroll
        for (int o2 = 16; o2 > 0; o2 >>= 1)
            mx = fmaxf(mx, __shfl_xor_sync(0xffffffffu, mx, o2));

        float sum = 0.f;
#pragma unroll
        for (int c = 0; c < 8; c++) {
            vv[c].x = __expf(vv[c].x - mx);
            vv[c].y = __expf(vv[c].y - mx);
            vv[c].z = __expf(vv[c].z - mx);
            vv[c].w = __expf(vv[c].w - mx);
            sum += vv[c].x + vv[c].y + vv[c].z + vv[c].w;
        }
#pragma unroll
        for (int o2 = 16; o2 > 0; o2 >>= 1)
            sum += __shfl_xor_sync(0xffffffffu, sum, o2);
        float inv = 1.0f / sum;

#pragma unroll
        for (int c = 0; c < 8; c++) {
            int col = c * 128 + lane * 4;
            vv[c].x *= inv; vv[c].y *= inv; vv[c].z *= inv; vv[c].w *= inv;
            *(float4*)&srow[col] = vv[c];
        }
    }

    // ---------- phase 3: O = P @ V, cp.async double-buffered V --------------
    wmma::fragment<wmma::accumulator, 16, 16, 8, float> oacc;
    wmma::fill_fragment(oacc, 0.f);
    buf = 0;
    for (int jt = 0; jt < 16; jt++) {
        if (jt + 1 < 16) {
            int nb = buf ^ 1;
            uint32_t d = sptr(&KVs[nb * 4352 + kvrow * 68 + kvcol]);
            const float* src = vbase + (long)(jt + 1) * 64 * CS;
#pragma unroll
            for (int i = 0; i < 4; i++) CP_ASYNC16(d + i * 16, src + i * 4);
            CP_COMMIT();
            CP_WAIT(1);
        } else {
            CP_WAIT(0);
        }
        __syncthreads();   // V tile visible; also orders phase-2 S writes (jt=0)

        const float* Vb = KVs + buf * 4352;
#pragma unroll
        for (int kk = 0; kk < 64; kk += 8) {
            wmma::fragment<wmma::matrix_a, 16, 16, 8, wmma::precision::tf32, wmma::row_major> af;
            wmma::fragment<wmma::matrix_b, 16, 16, 8, wmma::precision::tf32, wmma::row_major> bf;
            wmma::load_matrix_sync(af, &S[(wm * 16) * 1032 + jt * 64 + kk], 1032);
            wmma::load_matrix_sync(bf, &Vb[kk * 68 + wn * 16], 68);
#pragma unroll
            for (int e = 0; e < af.num_elements; e++) af.x[e] = wmma::__float_to_tf32(af.x[e]);
#pragma unroll
            for (int e = 0; e < bf.num_elements; e++) bf.x[e] = wmma::__float_to_tf32(bf.x[e]);
            wmma::mma_sync(oacc, af, bf, oacc);
        }
        __syncthreads();
        buf ^= 1;
    }

    // epilogue: stage O in Qs, gate with g, write
    wmma::store_matrix_sync(&Qs[(wm * 16) * 68 + wn * 16], oacc, 68, wmma::mem_row_major);
    __syncthreads();
    {
        int r = t >> 3, c = (t & 7) * 8;
        const float* gp = gate + (long)(i0 + r) * CS + h * HD + c;
        float*       op = o    + (long)(i0 + r) * CS + h * HD + c;
        float4 o0 = *(float4*)&Qs[r * 68 + c];
        float4 o1 = *(float4*)&Qs[r * 68 + c + 4];
        float4 g0 = *(const float4*)gp;
        float4 g1 = *(const float4*)(gp + 4);
        o0.x *= g0.x; o0.y *= g0.y; o0.z *= g0.z; o0.w *= g0.w;
        o1.x *= g1.x; o1.y *= g1.y; o1.z *= g1.z; o1.w *= g1.w;
        *(float4*)op       = o0;
        *(float4*)(op + 4) = o1;
    }
}

// ---------------- launcher ----------------------------------------------------
extern "C" void kernel_launch(void* const* d_in, const int* in_sizes, int n_in,
                              void* d_out, int out_size)
{
    const float* s    = (const float*)d_in[0];
    const float* k_in = (const float*)d_in[1];
    const float* mask = (const float*)d_in[2];
    const float* bias = (const float*)d_in[3];
    const float* Wq   = (const float*)d_in[4];
    const float* bq   = (const float*)d_in[5];
    const float* Wk   = (const float*)d_in[6];
    const float* Wv   = (const float*)d_in[7];
    const float* Wg   = (const float*)d_in[8];
    const float* Wo   = (const float*)d_in[9];
    const float* Wz   = (const float*)d_in[10];
    float* out = (float*)d_out;

    float *pq, *pk, *pv, *pg, *po, *patt;
    cudaGetSymbolAddress((void**)&pq,   g_q);
    cudaGetSymbolAddress((void**)&pk,   g_k);
    cudaGetSymbolAddress((void**)&pv,   g_v);
    cudaGetSymbolAddress((void**)&pg,   g_g);
    cudaGetSymbolAddress((void**)&po,   g_o);
    cudaGetSymbolAddress((void**)&patt, g_att);

    cudaFuncSetAttribute(proj4_kernel,
        cudaFuncAttributeMaxDynamicSharedMemorySize, GEMM_SMEM_BYTES);
    cudaFuncSetAttribute(gemm_wo_kernel,
        cudaFuncAttributeMaxDynamicSharedMemorySize, GEMM_SMEM_BYTES);
    cudaFuncSetAttribute(fused_attn_kernel,
        cudaFuncAttributeMaxDynamicSharedMemorySize, ATT_SMEM_BYTES);

    dim3 blk(256);

    // zbias: 512 MB bias read, HBM-bound
    zbias_kernel<<<SEQ, blk>>>(bias, Wz, mask, patt);

    // q,k,v,g projections: 64x128 tiles, 512 blocks, 2 CTAs/SM
    proj4_kernel<<<dim3(8, 16, 4), blk, GEMM_SMEM_BYTES>>>(
        s, k_in, Wq, bq, Wk, Wv, Wg, pq, pk, pv, pg);

    // fused attention: S=QK/8+z, softmax, O=PV, gate by g -> po
    fused_attn_kernel<<<dim3(32, NH), blk, ATT_SMEM_BYTES>>>(
        pq, pk, pv, pg, patt, po);

    // out = (g .* o) @ Wo^T : 64x128 tiles, 128 blocks
    gemm_wo_kernel<<<dim3(8, 16), blk, GEMM_SMEM_BYTES>>>(po, Wo, out);
}